// round 8
// baseline (speedup 1.0000x reference)
#include <cuda_runtime.h>
#include <cuda_bf16.h>
#include <math.h>
#include <stdint.h>

#define BATCHN 2
#define SEQL   4096
#define DMODEL 1024
#define NH     16
#define HD     64
#define CHUNKL 64
#define NCH    64
#define CONVD  3072
#define DINP   3088
#define BHN    (BATCHN*NH)
#define BSN    (BATCHN*SEQL)
#define K3     3072
#define NPAD_IP 3200

// ---------------- scratch ------------------------------------------------------
__device__ float g_xw[(size_t)BSN*DINP];
__device__ float g_Cm[(size_t)BHN*SEQL*HD];
__device__ float g_Bm[(size_t)BHN*SEQL*HD];
__device__ float g_Xv[(size_t)BHN*SEQL*HD];
__device__ float g_cumA[(size_t)BHN*SEQL];
__device__ float g_states[(size_t)BHN*NCH*HD*HD];   // per-chunk statesT [n][p]
__device__ float g_nstates[(size_t)BHN*NCH*HD*HD];  // entering statesT [n][p]
__device__ float g_Atot[BHN*NCH];
__device__ float g_ndec[BHN*NCH];
__device__ float g_nnew[BHN*NCH];
__device__ float g_Ydiag[(size_t)BHN*SEQL*HD];
__device__ float g_ndiag[(size_t)BHN*SEQL];
__device__ __nv_bfloat16 g_xs[(size_t)BSN*K3];
__device__ __nv_bfloat16 g_ws[(size_t)NPAD_IP*K3];
__device__ __nv_bfloat16 g_w2s[(size_t)DMODEL*K3];
__device__ __nv_bfloat16 g_ys[(size_t)BSN*K3];

// ---------------- helpers ------------------------------------------------------
__device__ __forceinline__ uint32_t smem_u32(const void* p) {
    uint32_t a;
    asm("{ .reg .u64 t; cvta.to.shared.u64 t, %1; cvt.u32.u64 %0, t; }" : "=r"(a) : "l"(p));
    return a;
}
#define CP16(dst, src)  asm volatile("cp.async.cg.shared.global [%0], [%1], 16;" :: "r"(dst), "l"(src) : "memory")
#define CP_COMMIT()     asm volatile("cp.async.commit_group;" ::: "memory")

__device__ __forceinline__ void ldm_x4(uint32_t* r, uint32_t addr) {
    asm volatile("ldmatrix.sync.aligned.m8n8.x4.shared.b16 {%0,%1,%2,%3}, [%4];"
        : "=r"(r[0]), "=r"(r[1]), "=r"(r[2]), "=r"(r[3]) : "r"(addr));
}
__device__ __forceinline__ void mma_bf16(float* c, const uint32_t* a, const uint32_t* b) {
    asm volatile("mma.sync.aligned.m16n8k16.row.col.f32.bf16.bf16.f32 "
        "{%0,%1,%2,%3},{%4,%5,%6,%7},{%8,%9},{%0,%1,%2,%3};"
        : "+f"(c[0]), "+f"(c[1]), "+f"(c[2]), "+f"(c[3])
        : "r"(a[0]), "r"(a[1]), "r"(a[2]), "r"(a[3]), "r"(b[0]), "r"(b[1]));
}

// ---------------- bf16 HMMA GEMM (BK=64, 3 stages) ------------------------------
#define BK    64
#define ROWE  72
#define NSTG  3
#define STGB  (2u * 128 * ROWE * 2)
#define OPB   (128u * ROWE * 2)

__global__ __launch_bounds__(256, 2) void mma_gemm_k(
    const __nv_bfloat16* __restrict__ A, const __nv_bfloat16* __restrict__ B,
    float* __restrict__ C, int K, int Nout, int ldc)
{
    extern __shared__ __align__(16) __nv_bfloat16 dsm[];

    const int tid  = threadIdx.x;
    const int lane = tid & 31;
    const int wid  = tid >> 5;
    const int wm   = wid & 1;
    const int wn   = wid >> 1;
    const int bm   = blockIdx.y * 128;
    const int bn   = blockIdx.x * 128;
    const int nk   = K / BK;

    float acc[4][4][4];
#pragma unroll
    for (int i = 0; i < 4; i++)
#pragma unroll
        for (int j = 0; j < 4; j++)
#pragma unroll
            for (int e = 0; e < 4; e++) acc[i][j][e] = 0.f;

    const int r0 = tid >> 3;
    const int c0 = (tid & 7) * 8;
    uint32_t sbase = smem_u32(dsm);

    uint32_t aoff[4];
#pragma unroll
    for (int mi = 0; mi < 4; mi++) {
        int row = wm * 64 + mi * 16 + (lane & 15);
        aoff[mi] = (uint32_t)(row * ROWE + (lane >> 4) * 8) * 2;
    }
    uint32_t boffp[2];
#pragma unroll
    for (int pi = 0; pi < 2; pi++) {
        int l2  = lane & 15;
        int grp = lane >> 4;
        int row = wn * 32 + (pi * 2 + grp) * 8 + (l2 & 7);
        boffp[pi] = (uint32_t)(row * ROWE + ((l2 >> 3) & 1) * 8) * 2;
    }

#pragma unroll
    for (int j = 0; j < 2; j++) {
        uint32_t sa = sbase + j * STGB, sb = sa + OPB;
        int k0 = j * BK;
#pragma unroll
        for (int i = 0; i < 4; i++) {
            int r = r0 + i * 32;
            CP16(sa + (uint32_t)(r * ROWE + c0) * 2, A + (size_t)(bm + r) * K + k0 + c0);
            CP16(sb + (uint32_t)(r * ROWE + c0) * 2, B + (size_t)(bn + r) * K + k0 + c0);
        }
        CP_COMMIT();
    }

    int st = 0;
#pragma unroll 1
    for (int kt = 0; kt < nk; kt++) {
        asm volatile("cp.async.wait_group 1;" ::: "memory");
        __syncthreads();

        int jn = kt + 2;
        if (jn < nk) {
            int st2 = st + 2; if (st2 >= 3) st2 -= 3;
            uint32_t sa = sbase + (uint32_t)st2 * STGB, sb = sa + OPB;
            int k0 = jn * BK;
#pragma unroll
            for (int i = 0; i < 4; i++) {
                int r = r0 + i * 32;
                CP16(sa + (uint32_t)(r * ROWE + c0) * 2, A + (size_t)(bm + r) * K + k0 + c0);
                CP16(sb + (uint32_t)(r * ROWE + c0) * 2, B + (size_t)(bn + r) * K + k0 + c0);
            }
        }
        CP_COMMIT();

        uint32_t sa = sbase + (uint32_t)st * STGB, sb = sa + OPB;

#pragma unroll
        for (int ksp = 0; ksp < 2; ksp++) {
            uint32_t a[2][4][4];
            uint32_t bp[2][2][4];
#pragma unroll
            for (int k2 = 0; k2 < 2; k2++) {
                uint32_t kadd = (uint32_t)((ksp * 2 + k2) * 16) * 2;
#pragma unroll
                for (int mi = 0; mi < 4; mi++) ldm_x4(a[k2][mi], sa + aoff[mi] + kadd);
#pragma unroll
                for (int pi = 0; pi < 2; pi++) ldm_x4(bp[k2][pi], sb + boffp[pi] + kadd);
            }
#pragma unroll
            for (int k2 = 0; k2 < 2; k2++)
#pragma unroll
                for (int mi = 0; mi < 4; mi++)
#pragma unroll
                    for (int ni = 0; ni < 4; ni++)
                        mma_bf16(acc[mi][ni], a[k2][mi], &bp[k2][ni >> 1][(ni & 1) * 2]);
        }
        if (++st == 3) st = 0;
    }

#pragma unroll
    for (int mi = 0; mi < 4; mi++) {
        int row = bm + wm * 64 + mi * 16 + (lane >> 2);
#pragma unroll
        for (int ni = 0; ni < 4; ni++) {
            int col = bn + wn * 32 + ni * 8 + (lane & 3) * 2;
            if (col < Nout) {
                *(float2*)(C + (size_t)row * ldc + col)       = make_float2(acc[mi][ni][0], acc[mi][ni][1]);
                *(float2*)(C + (size_t)(row + 8) * ldc + col) = make_float2(acc[mi][ni][2], acc[mi][ni][3]);
            }
        }
    }
}

// ---------------- fp32 -> bf16 hi/lo split --------------------------------------
__global__ void split_k(const float* __restrict__ src, __nv_bfloat16* __restrict__ dst,
                        int rows, int Kin, int rowsPad, int mode)
{
    int gi = blockIdx.x * blockDim.x + threadIdx.x;
    if (gi >= rowsPad * Kin) return;
    int r = gi / Kin, k = gi % Kin;
    float v = (r < rows) ? src[(size_t)r * Kin + k] : 0.f;
    __nv_bfloat16 hi = __float2bfloat16(v);
    __nv_bfloat16 lo = __float2bfloat16(v - __bfloat162float(hi));
    size_t b = (size_t)r * (3 * Kin) + k;
    dst[b] = hi;
    dst[b + Kin]     = mode ? lo : hi;
    dst[b + 2 * Kin] = mode ? hi : lo;
}

// --------------- tiled depthwise causal conv + split ----------------------------
__global__ __launch_bounds__(256) void conv_split_k(const float* __restrict__ cw,
                                                    const float* __restrict__ cb)
{
    __shared__ float tile[35][256];
    int bs_blk = blockIdx.x;
    int b = bs_blk >> 7;
    int srow0 = (bs_blk & 127) * 32;
    int ch0 = blockIdx.y * 256;
    int tid = threadIdx.x;
    int ch = ch0 + tid;

    float w0 = cw[ch * 4 + 0], w1 = cw[ch * 4 + 1];
    float w2 = cw[ch * 4 + 2], w3 = cw[ch * 4 + 3];
    float bias = cb[ch];

#pragma unroll
    for (int i = 0; i < 35; i++) {
        int row = srow0 - 3 + i;
        tile[i][tid] = (row >= 0) ? g_xw[((size_t)(b * SEQL + row)) * DINP + ch] : 0.f;
    }
    __syncthreads();

    int sect = ch >> 10;
    int h = (ch & 1023) >> 6;
    int n = ch & 63;
    float* dst = (sect == 0) ? g_Cm : (sect == 1) ? g_Bm : g_Xv;
    size_t dbase = ((size_t)(b * NH + h) * SEQL) * HD + n;

#pragma unroll
    for (int j = 0; j < 32; j++) {
        float acc = fmaf(tile[j][tid], w0,
                    fmaf(tile[j + 1][tid], w1,
                    fmaf(tile[j + 2][tid], w2,
                    fmaf(tile[j + 3][tid], w3, bias))));
        dst[dbase + (size_t)(srow0 + j) * HD] = acc;
    }
}

// --------------- per-chunk tile kernel (A-scale fused, float4 LDS layouts) --------
#define RP 68   // padded row (floats), 16B-aligned rows

__global__ __launch_bounds__(256) void chunk_k(const float* __restrict__ w_base)
{
    extern __shared__ float sh[];
    float (*sCT)[RP] = (float(*)[RP])sh;                  // C transposed [n][l]
    float (*sBT)[RP] = (float(*)[RP])(sh + 64 * RP);      // B transposed [n][l]
    float (*sB)[RP]  = (float(*)[RP])(sh + 2 * 64 * RP);  // B row-major [l][n]
    float (*sX)[RP]  = (float(*)[RP])(sh + 3 * 64 * RP);  // X row-major [l][p]
    float (*sGL)[RP] = (float(*)[RP])(sh + 4 * 64 * RP);  // GL row-major [i][j]
    __shared__ float scum[64];
    __shared__ float smn[64];
    __shared__ float sds[64];

    int bh = blockIdx.x >> 6;
    int c  = blockIdx.x & 63;
    int b  = bh >> 4;
    int h  = bh & 15;
    int tid = threadIdx.x;
    size_t base = ((size_t)bh * SEQL + (size_t)c * CHUNKL) * HD;
    size_t abase = (size_t)bh * SEQL + c * 64;

    {
        const float4* pC = (const float4*)(g_Cm + base);
        const float4* pB = (const float4*)(g_Bm + base);
        const float4* pX = (const float4*)(g_Xv + base);
        for (int i4 = tid; i4 < 1024; i4 += 256) {
            int l = i4 >> 4, n4 = (i4 & 15) * 4;
            float4 v = pC[i4];
            sCT[n4][l] = v.x; sCT[n4+1][l] = v.y; sCT[n4+2][l] = v.z; sCT[n4+3][l] = v.w;
            v = pB[i4];
            sBT[n4][l] = v.x; sBT[n4+1][l] = v.y; sBT[n4+2][l] = v.z; sBT[n4+3][l] = v.w;
            *(float4*)&sB[l][n4] = v;
            v = pX[i4];
            *(float4*)&sX[l][n4] = v;
        }
    }
    if (tid < 32) {
        float wbh = w_base[h];
        float v0 = g_xw[(size_t)(b * SEQL + c * 64 + 2 * tid)     * DINP + CONVD + h] * wbh;
        float v1 = g_xw[(size_t)(b * SEQL + c * 64 + 2 * tid + 1) * DINP + CONVD + h] * wbh;
        float s = v0 + v1;
#pragma unroll
        for (int o = 1; o < 32; o <<= 1) {
            float t = __shfl_up_sync(0xffffffffu, s, o);
            if (tid >= o) s += t;
        }
        float c1 = s, cc0 = s - v1;
        scum[2 * tid] = cc0; scum[2 * tid + 1] = c1;
        g_cumA[abase + 2 * tid] = cc0;
        g_cumA[abase + 2 * tid + 1] = c1;
        float mm = fminf(cc0, c1);
#pragma unroll
        for (int o = 1; o < 32; o <<= 1) {
            float t = __shfl_up_sync(0xffffffffu, mm, o);
            if (tid >= o) mm = fminf(mm, t);
        }
        float prev = __shfl_up_sync(0xffffffffu, mm, 1);
        if (tid == 0) prev = 1e30f;
        smn[2 * tid]     = fminf(prev, cc0);
        smn[2 * tid + 1] = fminf(prev, fminf(cc0, c1));
        float mtot = __shfl_sync(0xffffffffu, mm, 31);
        float d0 = __expf(mtot - cc0), d1 = __expf(mtot - c1);
        sds[2 * tid] = d0; sds[2 * tid + 1] = d1;
        float nd = d0 + d1;
#pragma unroll
        for (int o = 16; o; o >>= 1) nd += __shfl_xor_sync(0xffffffffu, nd, o);
        float ctot = __shfl_sync(0xffffffffu, c1, 31);
        if (tid == 0) { g_Atot[bh * NCH + c] = ctot; g_ndec[bh * NCH + c] = nd; }
    }
    __syncthreads();

    int tj = (tid & 15) * 4;
    int ti = (tid >> 4) * 4;

    // GEMM1: S[i][j] = sum_n C[i][n] B[j][n]  (via sCT, sBT, float4)
    {
        float r[4][4];
#pragma unroll
        for (int a = 0; a < 4; a++)
#pragma unroll
            for (int b2 = 0; b2 < 4; b2++) r[a][b2] = 0.f;
#pragma unroll 4
        for (int n = 0; n < 64; n++) {
            float4 cv = *(const float4*)&sCT[n][ti];
            float4 bv = *(const float4*)&sBT[n][tj];
            float cva[4] = {cv.x, cv.y, cv.z, cv.w};
            float bva[4] = {bv.x, bv.y, bv.z, bv.w};
#pragma unroll
            for (int a = 0; a < 4; a++)
#pragma unroll
                for (int b2 = 0; b2 < 4; b2++) r[a][b2] = fmaf(cva[a], bva[b2], r[a][b2]);
        }
#pragma unroll
        for (int a = 0; a < 4; a++) {
            int i = ti + a;
            float m = smn[i];
            float4 o;
            o.x = (tj + 0 <= i) ? r[a][0] * __expf(m - scum[tj + 0]) : 0.f;
            o.y = (tj + 1 <= i) ? r[a][1] * __expf(m - scum[tj + 1]) : 0.f;
            o.z = (tj + 2 <= i) ? r[a][2] * __expf(m - scum[tj + 2]) : 0.f;
            o.w = (tj + 3 <= i) ? r[a][3] * __expf(m - scum[tj + 3]) : 0.f;
            *(float4*)&sGL[i][tj] = o;
        }
    }
    if (tid < 64) {
        float s = 0.f;
        float m = smn[tid];
        for (int j = 0; j <= tid; j++) s += __expf(m - scum[j]);
        g_ndiag[abase + tid] = s;
    }
    __syncthreads();

    // GEMM2: Y[i][p] = sum_j GL[i][j] X[j][p]
    {
        float r[4][4];
#pragma unroll
        for (int a = 0; a < 4; a++)
#pragma unroll
            for (int b2 = 0; b2 < 4; b2++) r[a][b2] = 0.f;
#pragma unroll 4
        for (int j = 0; j < 64; j++) {
            float4 xv = *(const float4*)&sX[j][tj];
            float xva[4] = {xv.x, xv.y, xv.z, xv.w};
            float gl[4];
#pragma unroll
            for (int a = 0; a < 4; a++) gl[a] = sGL[ti + a][j];
#pragma unroll
            for (int a = 0; a < 4; a++)
#pragma unroll
                for (int b2 = 0; b2 < 4; b2++) r[a][b2] = fmaf(gl[a], xva[b2], r[a][b2]);
        }
#pragma unroll
        for (int a = 0; a < 4; a++)
            *(float4*)(g_Ydiag + base + (size_t)(ti + a) * 64 + tj)
                = make_float4(r[a][0], r[a][1], r[a][2], r[a][3]);
    }
    // GEMM3: statesT[n][p] = sum_l B[l][n] * ds_l * X[l][p]
    {
        float r[4][4];
#pragma unroll
        for (int a = 0; a < 4; a++)
#pragma unroll
            for (int b2 = 0; b2 < 4; b2++) r[a][b2] = 0.f;
#pragma unroll 4
        for (int l = 0; l < 64; l++) {
            float d = sds[l];
            float4 bv = *(const float4*)&sB[l][ti];
            float4 xv = *(const float4*)&sX[l][tj];
            float bva[4] = {bv.x, bv.y, bv.z, bv.w};
            float xva[4] = {xv.x * d, xv.y * d, xv.z * d, xv.w * d};
#pragma unroll
            for (int a = 0; a < 4; a++)
#pragma unroll
                for (int b2 = 0; b2 < 4; b2++) r[a][b2] = fmaf(bva[a], xva[b2], r[a][b2]);
        }
        size_t sb = ((size_t)bh * NCH + c) * 4096;
#pragma unroll
        for (int a = 0; a < 4; a++)
            *(float4*)(g_states + sb + (size_t)(ti + a) * 64 + tj)
                = make_float4(r[a][0], r[a][1], r[a][2], r[a][3]);
    }
}

// --------------- chunk recurrence scan (elementwise, layout-agnostic) -------------
__global__ void scan_k()
{
    int bh   = blockIdx.x >> 3;
    int part = blockIdx.x & 7;
    int tid  = threadIdx.x;
    int e0   = part * 512 + tid;
    size_t sb = (size_t)bh * NCH * 4096;

    float r0 = 0.f, r1 = 0.f;
    float minc = 0.f, cc = 0.f, nacc = 0.f;
    g_nstates[sb + e0] = 0.f;
    g_nstates[sb + e0 + 256] = 0.f;
    if (part == 0 && tid == 0) g_nnew[bh * NCH] = 0.f;
    for (int z = 0; z < 63; z++) {
        cc += g_Atot[bh * NCH + z];
        float m2 = fminf(minc, cc);
        float f = __expf(m2 - minc);
        float g = __expf(m2 - cc);
        r0 = r0 * f + g * g_states[sb + (size_t)z * 4096 + e0];
        r1 = r1 * f + g * g_states[sb + (size_t)z * 4096 + e0 + 256];
        minc = m2;
        g_nstates[sb + (size_t)(z + 1) * 4096 + e0] = r0;
        g_nstates[sb + (size_t)(z + 1) * 4096 + e0 + 256] = r1;
        if (part == 0 && tid == 0) {
            nacc = nacc * f + g * g_ndec[bh * NCH + z];
            g_nnew[bh * NCH + z + 1] = nacc;
        }
    }
}

// --------------- Y_off + combine + normalize + bf16 split -------------------------
__global__ __launch_bounds__(256) void yoff_k()
{
    __shared__ float sCT[64][RP];   // C transposed [n][l]
    __shared__ float sST[64][RP];   // entering statesT [n][p] (native layout)
    __shared__ float scum[64];
    __shared__ float sdo[64];

    int bh = blockIdx.x >> 6;
    int c  = blockIdx.x & 63;
    int b  = bh >> 4;
    int h  = bh & 15;
    int tid = threadIdx.x;
    size_t baseC = ((size_t)bh * SEQL + (size_t)c * 64) * HD;
    size_t baseS = ((size_t)bh * NCH + c) * 4096;

    {
        const float4* pC = (const float4*)(g_Cm + baseC);
        const float4* pS = (const float4*)(g_nstates + baseS);
        for (int i4 = tid; i4 < 1024; i4 += 256) {
            int l = i4 >> 4, n4 = (i4 & 15) * 4;
            float4 v = pC[i4];
            sCT[n4][l] = v.x; sCT[n4+1][l] = v.y; sCT[n4+2][l] = v.z; sCT[n4+3][l] = v.w;
            v = pS[i4];
            *(float4*)&sST[l][n4] = v;   // rows of statesT load linearly
        }
    }
    if (tid < 32) {
        float a0 = g_cumA[(size_t)bh * SEQL + c * 64 + 2 * tid];
        float a1 = g_cumA[(size_t)bh * SEQL + c * 64 + 2 * tid + 1];
        scum[2 * tid] = a0; scum[2 * tid + 1] = a1;
        float mx = fmaxf(a0, a1);
#pragma unroll
        for (int o = 16; o; o >>= 1) mx = fmaxf(mx, __shfl_xor_sync(0xffffffffu, mx, o));
        sdo[2 * tid]     = __expf(a0 - mx);
        sdo[2 * tid + 1] = __expf(a1 - mx);
    }
    __syncthreads();

    float nn = g_nnew[bh * NCH + c];
    int tl = (tid >> 4) * 4;
    int tp = (tid & 15) * 4;
    float r[4][4];
#pragma unroll
    for (int a = 0; a < 4; a++)
#pragma unroll
        for (int b2 = 0; b2 < 4; b2++) r[a][b2] = 0.f;
#pragma unroll 4
    for (int n = 0; n < 64; n++) {
        float4 cv = *(const float4*)&sCT[n][tl];
        float4 sv = *(const float4*)&sST[n][tp];
        float cva[4] = {cv.x, cv.y, cv.z, cv.w};
        float sva[4] = {sv.x, sv.y, sv.z, sv.w};
#pragma unroll
        for (int a = 0; a < 4; a++)
#pragma unroll
            for (int b2 = 0; b2 < 4; b2++) r[a][b2] = fmaf(cva[a], sva[b2], r[a][b2]);
    }
#pragma unroll
    for (int a = 0; a < 4; a++) {
        int l = tl + a;
        float d = sdo[l];
        float nm = g_ndiag[(size_t)bh * SEQL + c * 64 + l] + nn * d;
        float inv = 1.f / nm;
        int s = c * 64 + l;
        size_t rowb = ((size_t)b * SEQL + s) * K3 + h * 64;
        const float4 yv = *(const float4*)(g_Ydiag + baseC + (size_t)l * 64 + tp);
        float v0 = (yv.x + d * r[a][0]) * inv;
        float v1 = (yv.y + d * r[a][1]) * inv;
        float v2 = (yv.z + d * r[a][2]) * inv;
        float v3 = (yv.w + d * r[a][3]) * inv;
        __nv_bfloat16 h0 = __float2bfloat16(v0), h1 = __float2bfloat16(v1);
        __nv_bfloat16 h2 = __float2bfloat16(v2), h3 = __float2bfloat16(v3);
        __nv_bfloat16 l0 = __float2bfloat16(v0 - __bfloat162float(h0));
        __nv_bfloat16 l1 = __float2bfloat16(v1 - __bfloat162float(h1));
        __nv_bfloat16 l2 = __float2bfloat16(v2 - __bfloat162float(h2));
        __nv_bfloat16 l3 = __float2bfloat16(v3 - __bfloat162float(h3));
        __nv_bfloat162 hp0 = __halves2bfloat162(h0, h1), hp1 = __halves2bfloat162(h2, h3);
        __nv_bfloat162 lp0 = __halves2bfloat162(l0, l1), lp1 = __halves2bfloat162(l2, l3);
        uint2 hu, lu;
        hu.x = *(uint32_t*)&hp0; hu.y = *(uint32_t*)&hp1;
        lu.x = *(uint32_t*)&lp0; lu.y = *(uint32_t*)&lp1;
        *(uint2*)(g_ys + rowb + tp)              = hu;
        *(uint2*)(g_ys + rowb + tp + DMODEL)     = hu;
        *(uint2*)(g_ys + rowb + tp + 2 * DMODEL) = lu;
    }
}

// ------------------------------- launch ---------------------------------------------
extern "C" void kernel_launch(void* const* d_in, const int* in_sizes, int n_in,
                              void* d_out, int out_size)
{
    const float* x   = (const float*)d_in[0];
    const float* ipw = (const float*)d_in[1];
    const float* cw  = (const float*)d_in[2];
    const float* cb  = (const float*)d_in[3];
    const float* wb  = (const float*)d_in[4];
    const float* opw = (const float*)d_in[5];
    float* out = (float*)d_out;

    float *p_xw = nullptr;
    __nv_bfloat16 *p_xs, *p_ws, *p_w2s, *p_ys;
    cudaGetSymbolAddress((void**)&p_xw, g_xw);
    cudaGetSymbolAddress((void**)&p_xs, g_xs);
    cudaGetSymbolAddress((void**)&p_ws, g_ws);
    cudaGetSymbolAddress((void**)&p_w2s, g_w2s);
    cudaGetSymbolAddress((void**)&p_ys, g_ys);

    const int SMEM_CHUNK = 5 * 64 * RP * 4;   // 87040
    cudaFuncSetAttribute(chunk_k, cudaFuncAttributeMaxDynamicSharedMemorySize, SMEM_CHUNK);
    const int SMEM_GEMM = NSTG * (int)STGB;
    cudaFuncSetAttribute(mma_gemm_k, cudaFuncAttributeMaxDynamicSharedMemorySize, SMEM_GEMM);

    // 0) bf16 splits
    split_k<<<(BSN * DMODEL + 255) / 256, 256>>>(x, p_xs, BSN, DMODEL, BSN, 0);
    split_k<<<(NPAD_IP * DMODEL + 255) / 256, 256>>>(ipw, p_ws, DINP, DMODEL, NPAD_IP, 1);
    split_k<<<(DMODEL * DMODEL + 255) / 256, 256>>>(opw, p_w2s, DMODEL, DMODEL, DMODEL, 1);

    // 1) in_proj via HMMA
    {
        dim3 g(NPAD_IP / 128, BSN / 128);
        mma_gemm_k<<<g, 256, SMEM_GEMM>>>(p_xs, p_ws, p_xw, K3, DINP, DINP);
    }

    // 2) tiled conv + split
    {
        dim3 g(BSN / 32, CONVD / 256);
        conv_split_k<<<g, 256>>>(cw, cb);
    }

    // 3) per-chunk tiles
    chunk_k<<<BHN * NCH, 256, SMEM_CHUNK>>>(wb);

    // 4) chunk recurrence scan
    scan_k<<<BHN * 8, 256>>>();

    // 5) off-diagonal + normalize + fused bf16 split
    yoff_k<<<BHN * NCH, 256>>>();

    // 6) out_proj via HMMA
    {
        dim3 g(DMODEL / 128, BSN / 128);
        mma_gemm_k<<<g, 256, SMEM_GEMM>>>(p_ys, p_w2s, out, K3, DMODEL, DMODEL);
    }
}

// round 9
// speedup vs baseline: 1.0126x; 1.0126x over previous
#include <cuda_runtime.h>
#include <cuda_bf16.h>
#include <math.h>
#include <stdint.h>

#define BATCHN 2
#define SEQL   4096
#define DMODEL 1024
#define NH     16
#define HD     64
#define CHUNKL 64
#define NCH    64
#define CONVD  3072
#define DINP   3088
#define BHN    (BATCHN*NH)
#define BSN    (BATCHN*SEQL)
#define K3     3072
#define NPAD_IP 3200

// ---------------- scratch ------------------------------------------------------
__device__ float g_xw[(size_t)BSN*DINP];
__device__ float g_Cm[(size_t)BHN*SEQL*HD];
__device__ float g_cumA[(size_t)BHN*SEQL];
__device__ float g_states[(size_t)BHN*NCH*HD*HD];   // per-chunk statesT [n][p]
__device__ float g_nstates[(size_t)BHN*NCH*HD*HD];  // entering statesT [n][p]
__device__ float g_Atot[BHN*NCH];
__device__ float g_ndec[BHN*NCH];
__device__ float g_nnew[BHN*NCH];
__device__ float g_Ydiag[(size_t)BHN*SEQL*HD];
__device__ float g_ndiag[(size_t)BHN*SEQL];
__device__ __nv_bfloat16 g_xs[(size_t)BSN*K3];
__device__ __nv_bfloat16 g_ws[(size_t)NPAD_IP*K3];
__device__ __nv_bfloat16 g_w2s[(size_t)DMODEL*K3];
__device__ __nv_bfloat16 g_ys[(size_t)BSN*K3];

// ---------------- helpers ------------------------------------------------------
__device__ __forceinline__ uint32_t smem_u32(const void* p) {
    uint32_t a;
    asm("{ .reg .u64 t; cvta.to.shared.u64 t, %1; cvt.u32.u64 %0, t; }" : "=r"(a) : "l"(p));
    return a;
}
#define CP16(dst, src)  asm volatile("cp.async.cg.shared.global [%0], [%1], 16;" :: "r"(dst), "l"(src) : "memory")
#define CP_COMMIT()     asm volatile("cp.async.commit_group;" ::: "memory")

__device__ __forceinline__ void ldm_x4(uint32_t* r, uint32_t addr) {
    asm volatile("ldmatrix.sync.aligned.m8n8.x4.shared.b16 {%0,%1,%2,%3}, [%4];"
        : "=r"(r[0]), "=r"(r[1]), "=r"(r[2]), "=r"(r[3]) : "r"(addr));
}
__device__ __forceinline__ void mma_bf16(float* c, const uint32_t* a, const uint32_t* b) {
    asm volatile("mma.sync.aligned.m16n8k16.row.col.f32.bf16.bf16.f32 "
        "{%0,%1,%2,%3},{%4,%5,%6,%7},{%8,%9},{%0,%1,%2,%3};"
        : "+f"(c[0]), "+f"(c[1]), "+f"(c[2]), "+f"(c[3])
        : "r"(a[0]), "r"(a[1]), "r"(a[2]), "r"(a[3]), "r"(b[0]), "r"(b[1]));
}

// ---------------- bf16 HMMA GEMM (BK=64, 3 stages) ------------------------------
#define BK    64
#define ROWE  72
#define NSTG  3
#define STGB  (2u * 128 * ROWE * 2)
#define OPB   (128u * ROWE * 2)

__global__ __launch_bounds__(256, 2) void mma_gemm_k(
    const __nv_bfloat16* __restrict__ A, const __nv_bfloat16* __restrict__ B,
    float* __restrict__ C, int K, int Nout, int ldc)
{
    extern __shared__ __align__(16) __nv_bfloat16 dsm[];

    const int tid  = threadIdx.x;
    const int lane = tid & 31;
    const int wid  = tid >> 5;
    const int wm   = wid & 1;
    const int wn   = wid >> 1;
    const int bm   = blockIdx.y * 128;
    const int bn   = blockIdx.x * 128;
    const int nk   = K / BK;

    float acc[4][4][4];
#pragma unroll
    for (int i = 0; i < 4; i++)
#pragma unroll
        for (int j = 0; j < 4; j++)
#pragma unroll
            for (int e = 0; e < 4; e++) acc[i][j][e] = 0.f;

    const int r0 = tid >> 3;
    const int c0 = (tid & 7) * 8;
    uint32_t sbase = smem_u32(dsm);

    uint32_t aoff[4];
#pragma unroll
    for (int mi = 0; mi < 4; mi++) {
        int row = wm * 64 + mi * 16 + (lane & 15);
        aoff[mi] = (uint32_t)(row * ROWE + (lane >> 4) * 8) * 2;
    }
    uint32_t boffp[2];
#pragma unroll
    for (int pi = 0; pi < 2; pi++) {
        int l2  = lane & 15;
        int grp = lane >> 4;
        int row = wn * 32 + (pi * 2 + grp) * 8 + (l2 & 7);
        boffp[pi] = (uint32_t)(row * ROWE + ((l2 >> 3) & 1) * 8) * 2;
    }

#pragma unroll
    for (int j = 0; j < 2; j++) {
        uint32_t sa = sbase + j * STGB, sb = sa + OPB;
        int k0 = j * BK;
#pragma unroll
        for (int i = 0; i < 4; i++) {
            int r = r0 + i * 32;
            CP16(sa + (uint32_t)(r * ROWE + c0) * 2, A + (size_t)(bm + r) * K + k0 + c0);
            CP16(sb + (uint32_t)(r * ROWE + c0) * 2, B + (size_t)(bn + r) * K + k0 + c0);
        }
        CP_COMMIT();
    }

    int st = 0;
#pragma unroll 1
    for (int kt = 0; kt < nk; kt++) {
        asm volatile("cp.async.wait_group 1;" ::: "memory");
        __syncthreads();

        int jn = kt + 2;
        if (jn < nk) {
            int st2 = st + 2; if (st2 >= 3) st2 -= 3;
            uint32_t sa = sbase + (uint32_t)st2 * STGB, sb = sa + OPB;
            int k0 = jn * BK;
#pragma unroll
            for (int i = 0; i < 4; i++) {
                int r = r0 + i * 32;
                CP16(sa + (uint32_t)(r * ROWE + c0) * 2, A + (size_t)(bm + r) * K + k0 + c0);
                CP16(sb + (uint32_t)(r * ROWE + c0) * 2, B + (size_t)(bn + r) * K + k0 + c0);
            }
        }
        CP_COMMIT();

        uint32_t sa = sbase + (uint32_t)st * STGB, sb = sa + OPB;

#pragma unroll
        for (int ksp = 0; ksp < 2; ksp++) {
            uint32_t a[2][4][4];
            uint32_t bp[2][2][4];
#pragma unroll
            for (int k2 = 0; k2 < 2; k2++) {
                uint32_t kadd = (uint32_t)((ksp * 2 + k2) * 16) * 2;
#pragma unroll
                for (int mi = 0; mi < 4; mi++) ldm_x4(a[k2][mi], sa + aoff[mi] + kadd);
#pragma unroll
                for (int pi = 0; pi < 2; pi++) ldm_x4(bp[k2][pi], sb + boffp[pi] + kadd);
            }
#pragma unroll
            for (int k2 = 0; k2 < 2; k2++)
#pragma unroll
                for (int mi = 0; mi < 4; mi++)
#pragma unroll
                    for (int ni = 0; ni < 4; ni++)
                        mma_bf16(acc[mi][ni], a[k2][mi], &bp[k2][ni >> 1][(ni & 1) * 2]);
        }
        if (++st == 3) st = 0;
    }

#pragma unroll
    for (int mi = 0; mi < 4; mi++) {
        int row = bm + wm * 64 + mi * 16 + (lane >> 2);
#pragma unroll
        for (int ni = 0; ni < 4; ni++) {
            int col = bn + wn * 32 + ni * 8 + (lane & 3) * 2;
            if (col < Nout) {
                *(float2*)(C + (size_t)row * ldc + col)       = make_float2(acc[mi][ni][0], acc[mi][ni][1]);
                *(float2*)(C + (size_t)(row + 8) * ldc + col) = make_float2(acc[mi][ni][2], acc[mi][ni][3]);
            }
        }
    }
}

// ---------------- fp32 -> bf16 hi/lo split --------------------------------------
__global__ void split_k(const float* __restrict__ src, __nv_bfloat16* __restrict__ dst,
                        int rows, int Kin, int rowsPad, int mode)
{
    int gi = blockIdx.x * blockDim.x + threadIdx.x;
    if (gi >= rowsPad * Kin) return;
    int r = gi / Kin, k = gi % Kin;
    float v = (r < rows) ? src[(size_t)r * Kin + k] : 0.f;
    __nv_bfloat16 hi = __float2bfloat16(v);
    __nv_bfloat16 lo = __float2bfloat16(v - __bfloat162float(hi));
    size_t b = (size_t)r * (3 * Kin) + k;
    dst[b] = hi;
    dst[b + Kin]     = mode ? lo : hi;
    dst[b + 2 * Kin] = mode ? hi : lo;
}

// --------------- fused conv + per-chunk tile kernel --------------------------------
#define RP 68

__global__ __launch_bounds__(256) void chunk_k(const float* __restrict__ cw,
                                               const float* __restrict__ cb,
                                               const float* __restrict__ w_base)
{
    extern __shared__ float sh[];
    float (*sCT)[RP] = (float(*)[RP])sh;                  // C transposed [n][l]
    float (*sBT)[RP] = (float(*)[RP])(sh + 64 * RP);      // B transposed [n][l]
    float (*sB)[RP]  = (float(*)[RP])(sh + 2 * 64 * RP);  // B row-major [l][n]
    float (*sX)[RP]  = (float(*)[RP])(sh + 3 * 64 * RP);  // X row-major [l][p]
    float (*sGL)[RP] = (float(*)[RP])(sh + 4 * 64 * RP);  // GL row-major [i][j]
    __shared__ float scum[64];
    __shared__ float smn[64];
    __shared__ float sds[64];

    int bh = blockIdx.x >> 6;
    int c  = blockIdx.x & 63;
    int b  = bh >> 4;
    int h  = bh & 15;
    int tid = threadIdx.x;
    size_t base = ((size_t)bh * SEQL + (size_t)c * CHUNKL) * HD;
    size_t abase = (size_t)bh * SEQL + c * 64;

    // ---- conv phase: threads 0..191 each own one channel; warp 6 does A-scan ----
    if (tid < 192) {
        int n = tid & 63;
        int sect = tid >> 6;
        int ch = sect * 1024 + h * 64 + n;
        float w0 = cw[ch * 4 + 0], w1 = cw[ch * 4 + 1];
        float w2 = cw[ch * 4 + 2], w3 = cw[ch * 4 + 3];
        float bias = cb[ch];
        size_t rowbase = ((size_t)b * SEQL + (size_t)c * 64) * DINP + ch;

        float h0 = 0.f, h1 = 0.f, h2 = 0.f;
        if (c > 0) {
            h0 = g_xw[rowbase - 3 * (size_t)DINP];
            h1 = g_xw[rowbase - 2 * (size_t)DINP];
            h2 = g_xw[rowbase - 1 * (size_t)DINP];
        }
#pragma unroll 1
        for (int l0 = 0; l0 < 64; l0 += 8) {
            float xv[8];
#pragma unroll
            for (int k = 0; k < 8; k++)
                xv[k] = g_xw[rowbase + (size_t)(l0 + k) * DINP];
#pragma unroll
            for (int k = 0; k < 8; k++) {
                float o = fmaf(h0, w0, fmaf(h1, w1, fmaf(h2, w2, fmaf(xv[k], w3, bias))));
                int l = l0 + k;
                if (sect == 0) {
                    sCT[n][l] = o;
                    g_Cm[base + (size_t)l * 64 + n] = o;
                } else if (sect == 1) {
                    sBT[n][l] = o;
                    sB[l][n] = o;
                } else {
                    sX[l][n] = o;
                }
                h0 = h1; h1 = h2; h2 = xv[k];
            }
        }
    } else if (tid < 224) {
        int lane = tid & 31;
        float wbh = w_base[h];
        float v0 = g_xw[(size_t)(b * SEQL + c * 64 + 2 * lane)     * DINP + CONVD + h] * wbh;
        float v1 = g_xw[(size_t)(b * SEQL + c * 64 + 2 * lane + 1) * DINP + CONVD + h] * wbh;
        float s = v0 + v1;
#pragma unroll
        for (int o = 1; o < 32; o <<= 1) {
            float t = __shfl_up_sync(0xffffffffu, s, o);
            if (lane >= o) s += t;
        }
        float c1 = s, cc0 = s - v1;
        scum[2 * lane] = cc0; scum[2 * lane + 1] = c1;
        g_cumA[abase + 2 * lane] = cc0;
        g_cumA[abase + 2 * lane + 1] = c1;
        float mm = fminf(cc0, c1);
#pragma unroll
        for (int o = 1; o < 32; o <<= 1) {
            float t = __shfl_up_sync(0xffffffffu, mm, o);
            if (lane >= o) mm = fminf(mm, t);
        }
        float prev = __shfl_up_sync(0xffffffffu, mm, 1);
        if (lane == 0) prev = 1e30f;
        smn[2 * lane]     = fminf(prev, cc0);
        smn[2 * lane + 1] = fminf(prev, fminf(cc0, c1));
        float mtot = __shfl_sync(0xffffffffu, mm, 31);
        float d0 = __expf(mtot - cc0), d1 = __expf(mtot - c1);
        sds[2 * lane] = d0; sds[2 * lane + 1] = d1;
        float nd = d0 + d1;
#pragma unroll
        for (int o = 16; o; o >>= 1) nd += __shfl_xor_sync(0xffffffffu, nd, o);
        float ctot = __shfl_sync(0xffffffffu, c1, 31);
        if (lane == 0) { g_Atot[bh * NCH + c] = ctot; g_ndec[bh * NCH + c] = nd; }
    }
    __syncthreads();

    int tj = (tid & 15) * 4;
    int ti = (tid >> 4) * 4;

    // GEMM1: S[i][j] = sum_n C[i][n] B[j][n]
    {
        float r[4][4];
#pragma unroll
        for (int a = 0; a < 4; a++)
#pragma unroll
            for (int b2 = 0; b2 < 4; b2++) r[a][b2] = 0.f;
#pragma unroll 4
        for (int n = 0; n < 64; n++) {
            float4 cv = *(const float4*)&sCT[n][ti];
            float4 bv = *(const float4*)&sBT[n][tj];
            float cva[4] = {cv.x, cv.y, cv.z, cv.w};
            float bva[4] = {bv.x, bv.y, bv.z, bv.w};
#pragma unroll
            for (int a = 0; a < 4; a++)
#pragma unroll
                for (int b2 = 0; b2 < 4; b2++) r[a][b2] = fmaf(cva[a], bva[b2], r[a][b2]);
        }
#pragma unroll
        for (int a = 0; a < 4; a++) {
            int i = ti + a;
            float m = smn[i];
            float4 o;
            o.x = (tj + 0 <= i) ? r[a][0] * __expf(m - scum[tj + 0]) : 0.f;
            o.y = (tj + 1 <= i) ? r[a][1] * __expf(m - scum[tj + 1]) : 0.f;
            o.z = (tj + 2 <= i) ? r[a][2] * __expf(m - scum[tj + 2]) : 0.f;
            o.w = (tj + 3 <= i) ? r[a][3] * __expf(m - scum[tj + 3]) : 0.f;
            *(float4*)&sGL[i][tj] = o;
        }
    }
    if (tid < 64) {
        float s = 0.f;
        float m = smn[tid];
        for (int j = 0; j <= tid; j++) s += __expf(m - scum[j]);
        g_ndiag[abase + tid] = s;
    }
    __syncthreads();

    // GEMM2: Y[i][p] = sum_j GL[i][j] X[j][p]
    {
        float r[4][4];
#pragma unroll
        for (int a = 0; a < 4; a++)
#pragma unroll
            for (int b2 = 0; b2 < 4; b2++) r[a][b2] = 0.f;
#pragma unroll 4
        for (int j = 0; j < 64; j++) {
            float4 xv = *(const float4*)&sX[j][tj];
            float xva[4] = {xv.x, xv.y, xv.z, xv.w};
            float gl[4];
#pragma unroll
            for (int a = 0; a < 4; a++) gl[a] = sGL[ti + a][j];
#pragma unroll
            for (int a = 0; a < 4; a++)
#pragma unroll
                for (int b2 = 0; b2 < 4; b2++) r[a][b2] = fmaf(gl[a], xva[b2], r[a][b2]);
        }
#pragma unroll
        for (int a = 0; a < 4; a++)
            *(float4*)(g_Ydiag + base + (size_t)(ti + a) * 64 + tj)
                = make_float4(r[a][0], r[a][1], r[a][2], r[a][3]);
    }
    // GEMM3: statesT[n][p] = sum_l B[l][n] * ds_l * X[l][p]
    {
        float r[4][4];
#pragma unroll
        for (int a = 0; a < 4; a++)
#pragma unroll
            for (int b2 = 0; b2 < 4; b2++) r[a][b2] = 0.f;
#pragma unroll 4
        for (int l = 0; l < 64; l++) {
            float d = sds[l];
            float4 bv = *(const float4*)&sB[l][ti];
            float4 xv = *(const float4*)&sX[l][tj];
            float bva[4] = {bv.x, bv.y, bv.z, bv.w};
            float xva[4] = {xv.x * d, xv.y * d, xv.z * d, xv.w * d};
#pragma unroll
            for (int a = 0; a < 4; a++)
#pragma unroll
                for (int b2 = 0; b2 < 4; b2++) r[a][b2] = fmaf(bva[a], xva[b2], r[a][b2]);
        }
        size_t sb = ((size_t)bh * NCH + c) * 4096;
#pragma unroll
        for (int a = 0; a < 4; a++)
            *(float4*)(g_states + sb + (size_t)(ti + a) * 64 + tj)
                = make_float4(r[a][0], r[a][1], r[a][2], r[a][3]);
    }
}

// --------------- chunk recurrence scan --------------------------------------------
__global__ void scan_k()
{
    int bh   = blockIdx.x >> 3;
    int part = blockIdx.x & 7;
    int tid  = threadIdx.x;
    int e0   = part * 512 + tid;
    size_t sb = (size_t)bh * NCH * 4096;

    float r0 = 0.f, r1 = 0.f;
    float minc = 0.f, cc = 0.f, nacc = 0.f;
    g_nstates[sb + e0] = 0.f;
    g_nstates[sb + e0 + 256] = 0.f;
    if (part == 0 && tid == 0) g_nnew[bh * NCH] = 0.f;
    for (int z = 0; z < 63; z++) {
        cc += g_Atot[bh * NCH + z];
        float m2 = fminf(minc, cc);
        float f = __expf(m2 - minc);
        float g = __expf(m2 - cc);
        r0 = r0 * f + g * g_states[sb + (size_t)z * 4096 + e0];
        r1 = r1 * f + g * g_states[sb + (size_t)z * 4096 + e0 + 256];
        minc = m2;
        g_nstates[sb + (size_t)(z + 1) * 4096 + e0] = r0;
        g_nstates[sb + (size_t)(z + 1) * 4096 + e0 + 256] = r1;
        if (part == 0 && tid == 0) {
            nacc = nacc * f + g * g_ndec[bh * NCH + z];
            g_nnew[bh * NCH + z + 1] = nacc;
        }
    }
}

// --------------- Y_off + combine + normalize + bf16 split -------------------------
__global__ __launch_bounds__(256) void yoff_k()
{
    __shared__ float sCT[64][RP];   // C transposed [n][l]
    __shared__ float sST[64][RP];   // entering statesT [n][p]
    __shared__ float scum[64];
    __shared__ float sdo[64];

    int bh = blockIdx.x >> 6;
    int c  = blockIdx.x & 63;
    int b  = bh >> 4;
    int h  = bh & 15;
    int tid = threadIdx.x;
    size_t baseC = ((size_t)bh * SEQL + (size_t)c * 64) * HD;
    size_t baseS = ((size_t)bh * NCH + c) * 4096;

    {
        const float4* pC = (const float4*)(g_Cm + baseC);
        const float4* pS = (const float4*)(g_nstates + baseS);
        for (int i4 = tid; i4 < 1024; i4 += 256) {
            int l = i4 >> 4, n4 = (i4 & 15) * 4;
            float4 v = pC[i4];
            sCT[n4][l] = v.x; sCT[n4+1][l] = v.y; sCT[n4+2][l] = v.z; sCT[n4+3][l] = v.w;
            v = pS[i4];
            *(float4*)&sST[l][n4] = v;
        }
    }
    if (tid < 32) {
        float a0 = g_cumA[(size_t)bh * SEQL + c * 64 + 2 * tid];
        float a1 = g_cumA[(size_t)bh * SEQL + c * 64 + 2 * tid + 1];
        scum[2 * tid] = a0; scum[2 * tid + 1] = a1;
        float mx = fmaxf(a0, a1);
#pragma unroll
        for (int o = 16; o; o >>= 1) mx = fmaxf(mx, __shfl_xor_sync(0xffffffffu, mx, o));
        sdo[2 * tid]     = __expf(a0 - mx);
        sdo[2 * tid + 1] = __expf(a1 - mx);
    }
    __syncthreads();

    float nn = g_nnew[bh * NCH + c];
    int tl = (tid >> 4) * 4;
    int tp = (tid & 15) * 4;
    float r[4][4];
#pragma unroll
    for (int a = 0; a < 4; a++)
#pragma unroll
        for (int b2 = 0; b2 < 4; b2++) r[a][b2] = 0.f;
#pragma unroll 4
    for (int n = 0; n < 64; n++) {
        float4 cv = *(const float4*)&sCT[n][tl];
        float4 sv = *(const float4*)&sST[n][tp];
        float cva[4] = {cv.x, cv.y, cv.z, cv.w};
        float sva[4] = {sv.x, sv.y, sv.z, sv.w};
#pragma unroll
        for (int a = 0; a < 4; a++)
#pragma unroll
            for (int b2 = 0; b2 < 4; b2++) r[a][b2] = fmaf(cva[a], sva[b2], r[a][b2]);
    }
#pragma unroll
    for (int a = 0; a < 4; a++) {
        int l = tl + a;
        float d = sdo[l];
        float nm = g_ndiag[(size_t)bh * SEQL + c * 64 + l] + nn * d;
        float inv = 1.f / nm;
        int s = c * 64 + l;
        size_t rowb = ((size_t)b * SEQL + s) * K3 + h * 64;
        const float4 yv = *(const float4*)(g_Ydiag + baseC + (size_t)l * 64 + tp);
        float v0 = (yv.x + d * r[a][0]) * inv;
        float v1 = (yv.y + d * r[a][1]) * inv;
        float v2 = (yv.z + d * r[a][2]) * inv;
        float v3 = (yv.w + d * r[a][3]) * inv;
        __nv_bfloat16 h0 = __float2bfloat16(v0), h1 = __float2bfloat16(v1);
        __nv_bfloat16 h2 = __float2bfloat16(v2), h3 = __float2bfloat16(v3);
        __nv_bfloat16 l0 = __float2bfloat16(v0 - __bfloat162float(h0));
        __nv_bfloat16 l1 = __float2bfloat16(v1 - __bfloat162float(h1));
        __nv_bfloat16 l2 = __float2bfloat16(v2 - __bfloat162float(h2));
        __nv_bfloat16 l3 = __float2bfloat16(v3 - __bfloat162float(h3));
        __nv_bfloat162 hp0 = __halves2bfloat162(h0, h1), hp1 = __halves2bfloat162(h2, h3);
        __nv_bfloat162 lp0 = __halves2bfloat162(l0, l1), lp1 = __halves2bfloat162(l2, l3);
        uint2 hu, lu;
        hu.x = *(uint32_t*)&hp0; hu.y = *(uint32_t*)&hp1;
        lu.x = *(uint32_t*)&lp0; lu.y = *(uint32_t*)&lp1;
        *(uint2*)(g_ys + rowb + tp)              = hu;
        *(uint2*)(g_ys + rowb + tp + DMODEL)     = hu;
        *(uint2*)(g_ys + rowb + tp + 2 * DMODEL) = lu;
    }
}

// ------------------------------- launch ---------------------------------------------
extern "C" void kernel_launch(void* const* d_in, const int* in_sizes, int n_in,
                              void* d_out, int out_size)
{
    const float* x   = (const float*)d_in[0];
    const float* ipw = (const float*)d_in[1];
    const float* cw  = (const float*)d_in[2];
    const float* cb  = (const float*)d_in[3];
    const float* wb  = (const float*)d_in[4];
    const float* opw = (const float*)d_in[5];
    float* out = (float*)d_out;

    float *p_xw = nullptr;
    __nv_bfloat16 *p_xs, *p_ws, *p_w2s, *p_ys;
    cudaGetSymbolAddress((void**)&p_xw, g_xw);
    cudaGetSymbolAddress((void**)&p_xs, g_xs);
    cudaGetSymbolAddress((void**)&p_ws, g_ws);
    cudaGetSymbolAddress((void**)&p_w2s, g_w2s);
    cudaGetSymbolAddress((void**)&p_ys, g_ys);

    const int SMEM_CHUNK = 5 * 64 * RP * 4;   // 87040
    cudaFuncSetAttribute(chunk_k, cudaFuncAttributeMaxDynamicSharedMemorySize, SMEM_CHUNK);
    const int SMEM_GEMM = NSTG * (int)STGB;
    cudaFuncSetAttribute(mma_gemm_k, cudaFuncAttributeMaxDynamicSharedMemorySize, SMEM_GEMM);

    // 0) bf16 splits
    split_k<<<(BSN * DMODEL + 255) / 256, 256>>>(x, p_xs, BSN, DMODEL, BSN, 0);
    split_k<<<(NPAD_IP * DMODEL + 255) / 256, 256>>>(ipw, p_ws, DINP, DMODEL, NPAD_IP, 1);
    split_k<<<(DMODEL * DMODEL + 255) / 256, 256>>>(opw, p_w2s, DMODEL, DMODEL, DMODEL, 1);

    // 1) in_proj via HMMA
    {
        dim3 g(NPAD_IP / 128, BSN / 128);
        mma_gemm_k<<<g, 256, SMEM_GEMM>>>(p_xs, p_ws, p_xw, K3, DINP, DINP);
    }

    // 2) fused conv + per-chunk tiles
    chunk_k<<<BHN * NCH, 256, SMEM_CHUNK>>>(cw, cb, wb);

    // 3) chunk recurrence scan
    scan_k<<<BHN * 8, 256>>>();

    // 4) off-diagonal + normalize + fused bf16 split
    yoff_k<<<BHN * NCH, 256>>>();

    // 5) out_proj via HMMA
    {
        dim3 g(DMODEL / 128, BSN / 128);
        mma_gemm_k<<<g, 256, SMEM_GEMM>>>(p_ys, p_w2s, out, K3, DMODEL, DMODEL);
    }
}